// round 1
// baseline (speedup 1.0000x reference)
#include <cuda_runtime.h>
#include <cfloat>

#define B_  2
#define T_  2048
#define C_  768
#define H_  12
#define HD_ 64
#define BH_ (B_*H_)

// ln(2048)/sqrt(64)
#define QSC 0.9530773732699245f

// scratch (static device globals; no allocs allowed)
__device__ float g_q[(size_t)BH_*T_*HD_];   // [B,H,T,HD], pre-scaled by QSC*qm[d]
__device__ float g_k[(size_t)BH_*T_*HD_];
__device__ float g_v[(size_t)BH_*T_*HD_];
__device__ float g_y[(size_t)B_*T_*C_];     // [B,T,H*HD]

// ---------------------------------------------------------------------------
// Tiled SGEMM: C[M=4096, N=768] = A[4096,768] @ W[768,768]
// mode 0/1/2: scatter epilogue into g_q/g_k/g_v with [B,H,T,HD] layout
//             (mode 0 additionally scales by QSC*qm[d])
// mode 3    : A := g_y, plain row-major write to outp (d_out)
// ---------------------------------------------------------------------------
#define BM  128
#define BN  128
#define BKK 16

__global__ __launch_bounds__(256)
void sgemm_kernel(const float* __restrict__ A, const float* __restrict__ W,
                  float* __restrict__ outp, int mode, const float* __restrict__ qm)
{
    const int N = C_, K = C_;
    __shared__ float As[BKK][BM];
    __shared__ float Bs[BKK][BN];

    const float* Ap = (mode == 3) ? (const float*)g_y : A;

    int tid  = threadIdx.x;
    int row0 = blockIdx.y * BM;
    int col0 = blockIdx.x * BN;

    int a_r = tid >> 2;          // 0..63 (rows a_r, a_r+64)
    int a_c = (tid & 3) << 2;    // 0,4,8,12
    int b_r = tid >> 5;          // 0..7  (rows b_r, b_r+8)
    int b_c = (tid & 31) << 2;   // 0..124
    int ty  = tid >> 4, tx = tid & 15;

    float acc[8][8];
#pragma unroll
    for (int i = 0; i < 8; i++)
#pragma unroll
        for (int j = 0; j < 8; j++) acc[i][j] = 0.f;

    for (int k0 = 0; k0 < K; k0 += BKK) {
#pragma unroll
        for (int l = 0; l < 2; l++) {
            int r = a_r + l*64;
            float4 va = *(const float4*)&Ap[(size_t)(row0 + r)*K + k0 + a_c];
            As[a_c+0][r] = va.x; As[a_c+1][r] = va.y;
            As[a_c+2][r] = va.z; As[a_c+3][r] = va.w;
        }
#pragma unroll
        for (int l = 0; l < 2; l++) {
            int r = b_r + l*8;
            *(float4*)&Bs[r][b_c] = *(const float4*)&W[(size_t)(k0 + r)*N + col0 + b_c];
        }
        __syncthreads();

#pragma unroll
        for (int kk = 0; kk < BKK; kk++) {
            float4 a0 = *(const float4*)&As[kk][ty*8];
            float4 a1 = *(const float4*)&As[kk][ty*8+4];
            float4 b0 = *(const float4*)&Bs[kk][tx*8];
            float4 b1 = *(const float4*)&Bs[kk][tx*8+4];
            float ar[8] = {a0.x,a0.y,a0.z,a0.w,a1.x,a1.y,a1.z,a1.w};
            float br[8] = {b0.x,b0.y,b0.z,b0.w,b1.x,b1.y,b1.z,b1.w};
#pragma unroll
            for (int i = 0; i < 8; i++)
#pragma unroll
                for (int j = 0; j < 8; j++)
                    acc[i][j] += ar[i]*br[j];
        }
        __syncthreads();
    }

    if (mode == 3) {
#pragma unroll
        for (int i = 0; i < 8; i++) {
            int m = row0 + ty*8 + i;
            float* dst = &outp[(size_t)m*N + col0 + tx*8];
            *(float4*)dst     = make_float4(acc[i][0],acc[i][1],acc[i][2],acc[i][3]);
            *(float4*)(dst+4) = make_float4(acc[i][4],acc[i][5],acc[i][6],acc[i][7]);
        }
    } else {
        float* dstbase = (mode == 0) ? g_q : (mode == 1 ? g_k : g_v);
        int col = col0 + tx*8;
        int h = col >> 6, d = col & 63;   // 8 cols always within one head (8|64)
        float qs[8];
        if (mode == 0) {
#pragma unroll
            for (int j = 0; j < 8; j++) qs[j] = QSC * __ldg(&qm[d+j]);
        }
#pragma unroll
        for (int i = 0; i < 8; i++) {
            int m = row0 + ty*8 + i;
            int b = m >> 11, t = m & (T_-1);
            float* dst = &dstbase[(((size_t)b*H_ + h)*T_ + t)*HD_ + d];
            if (mode == 0) {
#pragma unroll
                for (int j = 0; j < 8; j++) dst[j] = acc[i][j]*qs[j];
            } else {
                *(float4*)dst     = make_float4(acc[i][0],acc[i][1],acc[i][2],acc[i][3]);
                *(float4*)(dst+4) = make_float4(acc[i][4],acc[i][5],acc[i][6],acc[i][7]);
            }
        }
    }
}

// ---------------------------------------------------------------------------
// Sparse top-4 causal attention. One thread = one query row.
// Streams K tiles through smem, tracks top-4 (value,index), then exact kth
// (4th largest of causal scores merged with the (T-1-i) masked zeros),
// gathers <=4 V rows weighted by tanh(score).
// ---------------------------------------------------------------------------
#define KT 64

__global__ __launch_bounds__(128)
void attn_kernel()
{
    __shared__ float ks[KT][HD_];
    int bh = blockIdx.y;
    // reverse x so heavy (large q0) CTAs launch first
    int q0 = (gridDim.x - 1 - blockIdx.x) * 128;
    int i  = q0 + threadIdx.x;

    const float* kb = g_k + (size_t)bh*T_*HD_;
    const float* vb = g_v + (size_t)bh*T_*HD_;

    float4 qr[16];
    {
        const float4* qp = (const float4*)(g_q + ((size_t)bh*T_ + i)*HD_);
#pragma unroll
        for (int d = 0; d < 16; d++) qr[d] = qp[d];
    }

    float w0=-FLT_MAX, w1=-FLT_MAX, w2=-FLT_MAX, w3=-FLT_MAX;
    int   i0=0, i1=0, i2=0, i3=0;

    int jmax = q0 + 128;
    int lr = threadIdx.x >> 1;
    int lc = (threadIdx.x & 1) << 5;
    for (int j0 = 0; j0 < jmax; j0 += KT) {
        // cooperative tile load: 64 rows x 64 floats
        {
            const float4* src = (const float4*)(kb + (size_t)(j0 + lr)*HD_ + lc);
            float4* dstp = (float4*)(&ks[lr][lc]);
#pragma unroll
            for (int u = 0; u < 8; u++) dstp[u] = src[u];
        }
        __syncthreads();

        int jend = i - j0 + 1;          // #keys with j <= i in this tile
        if (jend > KT) jend = KT;
        for (int jj = 0; jj < jend; jj++) {
            const float4* kp = (const float4*)&ks[jj][0];
            float s0=0.f, s1=0.f, s2=0.f, s3=0.f;   // 4 chains for ILP
#pragma unroll
            for (int d = 0; d < 16; d++) {
                float4 kv = kp[d];
                s0 += qr[d].x*kv.x;
                s1 += qr[d].y*kv.y;
                s2 += qr[d].z*kv.z;
                s3 += qr[d].w*kv.w;
            }
            float s = (s0+s1)+(s2+s3);
            int j = j0 + jj;
            if (s > w3) {
                w3 = s; i3 = j;
                if (w3 > w2) { float tf=w2; w2=w3; w3=tf; int ti=i2; i2=i3; i3=ti;
                    if (w2 > w1) { tf=w1; w1=w2; w2=tf; ti=i1; i1=i2; i2=ti;
                        if (w1 > w0) { tf=w0; w0=w1; w1=tf; ti=i0; i0=i1; i1=ti; } } }
            }
        }
        __syncthreads();
    }

    // kth = 4th largest of (causal scores U (T-1-i) zeros); contributors are
    // top-4 entries >= kth. Handles the last-4-rows edge (kth can be negative).
    int z  = T_ - 1 - i;
    int nz = z < 4 ? z : 4;
    int p  = (w0 > 0.f) + (w1 > 0.f) + (w2 > 0.f) + (w3 > 0.f);
    float kth;
    if (p >= 4)            kth = w3;
    else if (p + nz >= 4)  kth = 0.f;
    else kth = (nz == 0) ? w3 : (nz == 1 ? w2 : (nz == 2 ? w1 : w0));

    float4 acc[16];
#pragma unroll
    for (int d = 0; d < 16; d++) acc[d] = make_float4(0.f,0.f,0.f,0.f);

    float wv[4] = {w0,w1,w2,w3};
    int   iv[4] = {i0,i1,i2,i3};
#pragma unroll
    for (int m = 0; m < 4; m++) {
        if (wv[m] >= kth) {
            float wt = tanhf(wv[m]);
            const float4* vp = (const float4*)(vb + (size_t)iv[m]*HD_);
#pragma unroll
            for (int d = 0; d < 16; d++) {
                float4 vx = vp[d];
                acc[d].x += wt*vx.x; acc[d].y += wt*vx.y;
                acc[d].z += wt*vx.z; acc[d].w += wt*vx.w;
            }
        }
    }

    int b = bh / H_, h = bh % H_;
    float4* yp = (float4*)(g_y + ((size_t)(b*T_ + i))*C_ + h*HD_);
#pragma unroll
    for (int d = 0; d < 16; d++) yp[d] = acc[d];
}

// ---------------------------------------------------------------------------
extern "C" void kernel_launch(void* const* d_in, const int* in_sizes, int n_in,
                              void* d_out, int out_size)
{
    const float* x  = (const float*)d_in[0];
    const float* Wq = (const float*)d_in[1];
    const float* Wk = (const float*)d_in[2];
    const float* Wv = (const float*)d_in[3];
    const float* Wp = (const float*)d_in[4];
    const float* qm = (const float*)d_in[5];
    float* out = (float*)d_out;

    dim3 gg(C_/BN, (B_*T_)/BM);   // (6, 32)
    sgemm_kernel<<<gg, 256>>>(x, Wq, nullptr, 0, qm);
    sgemm_kernel<<<gg, 256>>>(x, Wk, nullptr, 1, qm);
    sgemm_kernel<<<gg, 256>>>(x, Wv, nullptr, 2, qm);
    attn_kernel<<<dim3(T_/128, BH_), 128>>>();
    sgemm_kernel<<<gg, 256>>>(nullptr, Wp, out, 3, qm);
}

// round 2
// speedup vs baseline: 1.4018x; 1.4018x over previous
#include <cuda_runtime.h>
#include <cfloat>

#define B_  2
#define T_  2048
#define C_  768
#define H_  12
#define HD_ 64
#define BH_ (B_*H_)

// ln(2048)/sqrt(64)
#define QSC 0.9530773732699245f

// scratch (static device globals; no allocs allowed)
__device__ float g_q[(size_t)BH_*HD_*T_];   // [bh][d][t]  pre-scaled by QSC*qm[d]
__device__ float g_k[(size_t)BH_*HD_*T_];   // [bh][d][t]
__device__ float g_v[(size_t)BH_*T_*HD_];   // [bh][t][d]
__device__ float g_y[(size_t)B_*T_*C_];     // [b][t][h*HD]

#define BM  128
#define BN  128
#define BKK 16

// ---------------------------------------------------------------------------
// Shared SGEMM tile compute: acc[8][8] for C[M,N] = A @ W, M=4096, N=K=768
// ---------------------------------------------------------------------------
__device__ __forceinline__ void gemm_tile(const float* __restrict__ Ap,
                                          const float* __restrict__ W,
                                          float acc[8][8],
                                          float As[BKK][BM], float Bs[BKK][BN],
                                          int row0, int col0)
{
    const int N = C_, K = C_;
    int tid = threadIdx.x;
    int a_r = tid >> 2;
    int a_c = (tid & 3) << 2;
    int b_r = tid >> 5;
    int b_c = (tid & 31) << 2;
    int ty  = tid >> 4, tx = tid & 15;

#pragma unroll
    for (int i = 0; i < 8; i++)
#pragma unroll
        for (int j = 0; j < 8; j++) acc[i][j] = 0.f;

    for (int k0 = 0; k0 < K; k0 += BKK) {
#pragma unroll
        for (int l = 0; l < 2; l++) {
            int r = a_r + l*64;
            float4 va = *(const float4*)&Ap[(size_t)(row0 + r)*K + k0 + a_c];
            As[a_c+0][r] = va.x; As[a_c+1][r] = va.y;
            As[a_c+2][r] = va.z; As[a_c+3][r] = va.w;
        }
#pragma unroll
        for (int l = 0; l < 2; l++) {
            int r = b_r + l*8;
            *(float4*)&Bs[r][b_c] = *(const float4*)&W[(size_t)(k0 + r)*N + col0 + b_c];
        }
        __syncthreads();

#pragma unroll
        for (int kk = 0; kk < BKK; kk++) {
            float4 a0 = *(const float4*)&As[kk][ty*8];
            float4 a1 = *(const float4*)&As[kk][ty*8+4];
            float4 b0 = *(const float4*)&Bs[kk][tx*8];
            float4 b1 = *(const float4*)&Bs[kk][tx*8+4];
            float ar[8] = {a0.x,a0.y,a0.z,a0.w,a1.x,a1.y,a1.z,a1.w};
            float br[8] = {b0.x,b0.y,b0.z,b0.w,b1.x,b1.y,b1.z,b1.w};
#pragma unroll
            for (int i = 0; i < 8; i++)
#pragma unroll
                for (int j = 0; j < 8; j++)
                    acc[i][j] += ar[i]*br[j];
        }
        __syncthreads();
    }
}

// ---------------------------------------------------------------------------
// Fused QKV GEMM: blockIdx.z selects Wq/Wk/Wv and epilogue.
//  z=0: g_q[bh][d][t] = acc * QSC*qm[d]   (transposed write)
//  z=1: g_k[bh][d][t] = acc               (transposed write)
//  z=2: g_v[bh][t][d] = acc               (row write)
// ---------------------------------------------------------------------------
__global__ __launch_bounds__(256)
void sgemm_qkv(const float* __restrict__ x,
               const float* __restrict__ Wq, const float* __restrict__ Wk,
               const float* __restrict__ Wv, const float* __restrict__ qm)
{
    __shared__ float As[BKK][BM];
    __shared__ float Bs[BKK][BN];
    int mode = blockIdx.z;
    const float* W = (mode == 0) ? Wq : (mode == 1 ? Wk : Wv);
    int row0 = blockIdx.y * BM;
    int col0 = blockIdx.x * BN;

    float acc[8][8];
    gemm_tile(x, W, acc, As, Bs, row0, col0);

    int tid = threadIdx.x;
    int ty = tid >> 4, tx = tid & 15;
    int col = col0 + tx*8;          // global out-channel
    int h = col >> 6, d0 = col & 63;
    int m0 = row0 + ty*8;
    int b = m0 >> 11, t0 = m0 & (T_-1);

    if (mode == 2) {
        float* dst0 = &g_v[(((size_t)(b*H_ + h)*T_)) * HD_];
#pragma unroll
        for (int i = 0; i < 8; i++) {
            float* dst = dst0 + (size_t)(t0 + i)*HD_ + d0;
            *(float4*)dst     = make_float4(acc[i][0],acc[i][1],acc[i][2],acc[i][3]);
            *(float4*)(dst+4) = make_float4(acc[i][4],acc[i][5],acc[i][6],acc[i][7]);
        }
    } else {
        float* dstbase = (mode == 0) ? g_q : g_k;
        size_t base = (size_t)(b*H_ + h)*HD_*T_;
#pragma unroll
        for (int j = 0; j < 8; j++) {
            float sc = (mode == 0) ? QSC * __ldg(&qm[d0+j]) : 1.f;
            float* dst = &dstbase[base + (size_t)(d0+j)*T_ + t0];
            *(float4*)dst     = make_float4(acc[0][j]*sc,acc[1][j]*sc,acc[2][j]*sc,acc[3][j]*sc);
            *(float4*)(dst+4) = make_float4(acc[4][j]*sc,acc[5][j]*sc,acc[6][j]*sc,acc[7][j]*sc);
        }
    }
}

// Output projection: out[M,768] = g_y @ Wp
__global__ __launch_bounds__(256)
void sgemm_proj(const float* __restrict__ Wp, float* __restrict__ outp)
{
    __shared__ float As[BKK][BM];
    __shared__ float Bs[BKK][BN];
    int row0 = blockIdx.y * BM;
    int col0 = blockIdx.x * BN;

    float acc[8][8];
    gemm_tile(g_y, Wp, acc, As, Bs, row0, col0);

    int tid = threadIdx.x;
    int ty = tid >> 4, tx = tid & 15;
#pragma unroll
    for (int i = 0; i < 8; i++) {
        int m = row0 + ty*8 + i;
        float* dst = &outp[(size_t)m*C_ + col0 + tx*8];
        *(float4*)dst     = make_float4(acc[i][0],acc[i][1],acc[i][2],acc[i][3]);
        *(float4*)(dst+4) = make_float4(acc[i][4],acc[i][5],acc[i][6],acc[i][7]);
    }
}

// ---------------------------------------------------------------------------
// GEMM-tiled sparse top-4 causal attention.
// CTA: 64 queries x all keys (tiles of 64). 256 threads = 16 qrow x 16 kcol,
// each thread computes 4q x 4k scores per tile, keeps per-key-slice top-4 in
// registers; one smem merge at the end; V gather weighted by tanh.
// ---------------------------------------------------------------------------
#define MQ 64
#define NK 64

struct AttnSmem {
    union {
        struct { float Qs[64][64]; float Ks[64][64]; } t;
        struct { float cv[64][65]; int ci[64][65]; } c;   // cand[cand_slot][q]
    } u;
    float wsel[64][4];
    int   isel[64][4];
};

#define INS4(W0,W1,W2,W3,I0,I1,I2,I3,s,j)                                   \
    if ((s) > W3) { W3=(s); I3=(j);                                         \
        if (W3>W2){float tf_=W2;W2=W3;W3=tf_;int ti_=I2;I2=I3;I3=ti_;       \
            if (W2>W1){tf_=W1;W1=W2;W2=tf_;ti_=I1;I1=I2;I2=ti_;             \
                if (W1>W0){tf_=W0;W0=W1;W1=tf_;ti_=I0;I0=I1;I1=ti_;}}}}

__global__ __launch_bounds__(256)
void attn_kernel()
{
    __shared__ AttnSmem sm;
    int bh  = blockIdx.y;
    int q0  = (gridDim.x - 1 - blockIdx.x) * MQ;   // heavy CTAs first
    int tid = threadIdx.x;
    int qrow = tid >> 4;     // 0..15
    int kcol = tid & 15;     // 0..15

    const float* qb = g_q + (size_t)bh*HD_*T_;
    const float* kb = g_k + (size_t)bh*HD_*T_;
    const float* vb = g_v + (size_t)bh*T_*HD_;

    // Load Q tile: Qs[d][q] <- qb[d][q0+q]  (contiguous copy, no transpose)
    {
        int r  = tid >> 2;
        int c0 = (tid & 3) * 16;
        const float4* src = (const float4*)(qb + (size_t)r*T_ + q0 + c0);
        float4* dst = (float4*)&sm.u.t.Qs[r][c0];
#pragma unroll
        for (int uu = 0; uu < 4; uu++) dst[uu] = src[uu];
    }

    float w[4][4], wi[4][4];
    int  id[4][4];
#pragma unroll
    for (int u = 0; u < 4; u++)
#pragma unroll
        for (int m = 0; m < 4; m++) { w[u][m] = -FLT_MAX; id[u][m] = 0; (void)wi; }

    const int ntiles = q0/NK + 1;
    for (int tile = 0; tile < ntiles; tile++) {
        int j0 = tile*NK;
        __syncthreads();
        {
            int r  = tid >> 2;
            int c0 = (tid & 3) * 16;
            const float4* src = (const float4*)(kb + (size_t)r*T_ + j0 + c0);
            float4* dst = (float4*)&sm.u.t.Ks[r][c0];
#pragma unroll
            for (int uu = 0; uu < 4; uu++) dst[uu] = src[uu];
        }
        __syncthreads();

        float accv[4][4];
#pragma unroll
        for (int u = 0; u < 4; u++)
#pragma unroll
            for (int v = 0; v < 4; v++) accv[u][v] = 0.f;

#pragma unroll 16
        for (int kk = 0; kk < 64; kk++) {
            float4 av = *(const float4*)&sm.u.t.Qs[kk][qrow*4];
            float4 bv = *(const float4*)&sm.u.t.Ks[kk][kcol*4];
            accv[0][0] += av.x*bv.x; accv[0][1] += av.x*bv.y;
            accv[0][2] += av.x*bv.z; accv[0][3] += av.x*bv.w;
            accv[1][0] += av.y*bv.x; accv[1][1] += av.y*bv.y;
            accv[1][2] += av.y*bv.z; accv[1][3] += av.y*bv.w;
            accv[2][0] += av.z*bv.x; accv[2][1] += av.z*bv.y;
            accv[2][2] += av.z*bv.z; accv[2][3] += av.z*bv.w;
            accv[3][0] += av.w*bv.x; accv[3][1] += av.w*bv.y;
            accv[3][2] += av.w*bv.z; accv[3][3] += av.w*bv.w;
        }

        int jb = j0 + kcol*4;
        if (tile == ntiles-1) {
#pragma unroll
            for (int u = 0; u < 4; u++) {
                int qg = q0 + qrow*4 + u;
#pragma unroll
                for (int v = 0; v < 4; v++) {
                    float s = accv[u][v]; int j = jb + v;
                    if (j <= qg) { INS4(w[u][0],w[u][1],w[u][2],w[u][3],
                                        id[u][0],id[u][1],id[u][2],id[u][3], s, j); }
                }
            }
        } else {
#pragma unroll
            for (int u = 0; u < 4; u++) {
#pragma unroll
                for (int v = 0; v < 4; v++) {
                    float s = accv[u][v]; int j = jb + v;
                    INS4(w[u][0],w[u][1],w[u][2],w[u][3],
                         id[u][0],id[u][1],id[u][2],id[u][3], s, j);
                }
            }
        }
    }

    __syncthreads();   // done reading Qs/Ks; safe to overlay candidates

    // write per-thread candidates: cand[kcol*4+m][qrow*4+u]
#pragma unroll
    for (int u = 0; u < 4; u++) {
        int q = qrow*4 + u;
#pragma unroll
        for (int m = 0; m < 4; m++) {
            int c = kcol*4 + m;
            sm.u.c.cv[c][q] = w[u][m];
            sm.u.c.ci[c][q] = id[u][m];
        }
    }
    __syncthreads();

    if (tid < 64) {
        int q = tid, qi = q0 + q;
        float m0=-FLT_MAX, m1=-FLT_MAX, m2=-FLT_MAX, m3=-FLT_MAX;
        int   j0_=0, j1_=0, j2_=0, j3_=0;
        for (int c = 0; c < 64; c++) {
            float s = sm.u.c.cv[c][q];
            int   j = sm.u.c.ci[c][q];
            INS4(m0,m1,m2,m3,j0_,j1_,j2_,j3_, s, j);
        }
        // kth = 4th largest of (causal scores U (T-1-i) masked zeros)
        int z  = T_ - 1 - qi;
        int nz = z < 4 ? z : 4;
        int p  = (m0 > 0.f) + (m1 > 0.f) + (m2 > 0.f) + (m3 > 0.f);
        float kth;
        if (p >= 4)            kth = m3;
        else if (p + nz >= 4)  kth = 0.f;
        else kth = (nz == 0) ? m3 : (nz == 1 ? m2 : (nz == 2 ? m1 : m0));

        sm.wsel[q][0] = (m0 >= kth) ? tanhf(m0) : 0.f;  sm.isel[q][0] = j0_;
        sm.wsel[q][1] = (m1 >= kth) ? tanhf(m1) : 0.f;  sm.isel[q][1] = j1_;
        sm.wsel[q][2] = (m2 >= kth) ? tanhf(m2) : 0.f;  sm.isel[q][2] = j2_;
        sm.wsel[q][3] = (m3 >= kth) ? tanhf(m3) : 0.f;  sm.isel[q][3] = j3_;
    }
    __syncthreads();

    // V gather + Y write: thread = (q, 16-dim group)
    {
        int q = tid >> 2, g = tid & 3;
        float4 a0 = make_float4(0,0,0,0), a1 = a0, a2 = a0, a3 = a0;
#pragma unroll
        for (int m = 0; m < 4; m++) {
            float wt = sm.wsel[q][m];
            const float4* vp = (const float4*)(vb + (size_t)sm.isel[q][m]*HD_ + g*16);
            float4 v0 = vp[0], v1 = vp[1], v2 = vp[2], v3 = vp[3];
            a0.x += wt*v0.x; a0.y += wt*v0.y; a0.z += wt*v0.z; a0.w += wt*v0.w;
            a1.x += wt*v1.x; a1.y += wt*v1.y; a1.z += wt*v1.z; a1.w += wt*v1.w;
            a2.x += wt*v2.x; a2.y += wt*v2.y; a2.z += wt*v2.z; a2.w += wt*v2.w;
            a3.x += wt*v3.x; a3.y += wt*v3.y; a3.z += wt*v3.z; a3.w += wt*v3.w;
        }
        int b = bh / H_, h = bh % H_;
        float4* yp = (float4*)(g_y + ((size_t)b*T_ + q0 + q)*C_ + h*HD_ + g*16);
        yp[0] = a0; yp[1] = a1; yp[2] = a2; yp[3] = a3;
    }
}

// ---------------------------------------------------------------------------
extern "C" void kernel_launch(void* const* d_in, const int* in_sizes, int n_in,
                              void* d_out, int out_size)
{
    const float* x  = (const float*)d_in[0];
    const float* Wq = (const float*)d_in[1];
    const float* Wk = (const float*)d_in[2];
    const float* Wv = (const float*)d_in[3];
    const float* Wp = (const float*)d_in[4];
    const float* qm = (const float*)d_in[5];
    float* out = (float*)d_out;

    sgemm_qkv<<<dim3(C_/BN, (B_*T_)/BM, 3), 256>>>(x, Wq, Wk, Wv, qm);
    attn_kernel<<<dim3(T_/MQ, BH_), 256>>>();
    sgemm_proj<<<dim3(C_/BN, (B_*T_)/BM), 256>>>(Wp, out);
}

// round 3
// speedup vs baseline: 1.5570x; 1.1107x over previous
#include <cuda_runtime.h>
#include <cfloat>

#define B_  2
#define T_  2048
#define C_  768
#define H_  12
#define HD_ 64
#define BH_ (B_*H_)

// ln(2048)/sqrt(64)
#define QSC 0.9530773732699245f

// scratch (static device globals; no allocs allowed)
__device__ float g_q[(size_t)BH_*HD_*T_];   // [bh][d][t], pre-scaled by QSC*qm[d]
__device__ float g_k[(size_t)BH_*HD_*T_];   // [bh][d][t]
__device__ float g_v[(size_t)BH_*T_*HD_];   // [bh][t][d]
__device__ float g_y[(size_t)B_*T_*C_];     // [b][t][h*HD]

// ---------------------------------------------------------------------------
// cp.async helpers
// ---------------------------------------------------------------------------
__device__ __forceinline__ void cpa16(void* dst, const void* src) {
    unsigned s = (unsigned)__cvta_generic_to_shared(dst);
    asm volatile("cp.async.cg.shared.global [%0], [%1], 16;\n" :: "r"(s), "l"(src));
}
__device__ __forceinline__ void cpa_commit() {
    asm volatile("cp.async.commit_group;\n");
}
template<int N> __device__ __forceinline__ void cpa_wait() {
    asm volatile("cp.async.wait_group %0;\n" :: "n"(N));
}

// ---------------------------------------------------------------------------
// GEMM: C[4096,768] = A[4096,768] @ W[768,768], 64x128 tiles, BK=16,
// cp.async double-buffered. 256 threads, 4x8 micro-tile (split cols for
// conflict-free LDS). mode(blockIdx.z or proj): 0=q(transposed+scaled),
// 1=k(transposed), 2=v, proj flag => plain write to outp.
// ---------------------------------------------------------------------------
#define GBM 64
#define GBN 128
#define GBK 16

__global__ __launch_bounds__(256)
void gemm64(const float* __restrict__ Asrc,
            const float* __restrict__ W0, const float* __restrict__ W1,
            const float* __restrict__ W2, const float* __restrict__ qm,
            float* __restrict__ outp, int proj)
{
    __shared__ float As[2][GBM][GBK];
    __shared__ float Bs[2][GBK][GBN];

    int mode = proj ? 3 : blockIdx.z;
    const float* W = (mode == 1) ? W1 : (mode == 2 ? W2 : W0);
    const float* A = proj ? (const float*)g_y : Asrc;

    int tid  = threadIdx.x;
    int row0 = blockIdx.y * GBM;
    int col0 = blockIdx.x * GBN;

    int ar = tid >> 2, ac = (tid & 3) * 4;       // A tile: 64 rows x 16 cols
    int br = tid >> 4, bc = (tid & 15) * 8;      // B tile: 16 rows x 128 cols
    int qrow = tid >> 4, tx = tid & 15;

    // preload k-slice 0
    cpa16(&As[0][ar][ac],    &A[(size_t)(row0 + ar)*C_ + ac]);
    cpa16(&Bs[0][br][bc],    &W[(size_t)br*C_ + col0 + bc]);
    cpa16(&Bs[0][br][bc+4],  &W[(size_t)br*C_ + col0 + bc + 4]);
    cpa_commit();

    float acc[4][8];
#pragma unroll
    for (int i = 0; i < 4; i++)
#pragma unroll
        for (int j = 0; j < 8; j++) acc[i][j] = 0.f;

    const int NIT = C_ / GBK;    // 48
    for (int it = 0; it < NIT; it++) {
        if (it + 1 < NIT) {
            int nb = (it + 1) & 1;
            int k0 = (it + 1) * GBK;
            cpa16(&As[nb][ar][ac],   &A[(size_t)(row0 + ar)*C_ + k0 + ac]);
            cpa16(&Bs[nb][br][bc],   &W[(size_t)(k0 + br)*C_ + col0 + bc]);
            cpa16(&Bs[nb][br][bc+4], &W[(size_t)(k0 + br)*C_ + col0 + bc + 4]);
            cpa_commit();
            cpa_wait<1>();
        } else {
            cpa_wait<0>();
        }
        __syncthreads();

        int cb = it & 1;
#pragma unroll
        for (int kb = 0; kb < 4; kb++) {
            float a0v[4], a1v[4], a2v[4], a3v[4];
            *(float4*)a0v = *(const float4*)&As[cb][qrow*4+0][kb*4];
            *(float4*)a1v = *(const float4*)&As[cb][qrow*4+1][kb*4];
            *(float4*)a2v = *(const float4*)&As[cb][qrow*4+2][kb*4];
            *(float4*)a3v = *(const float4*)&As[cb][qrow*4+3][kb*4];
#pragma unroll
            for (int kl = 0; kl < 4; kl++) {
                float4 b0 = *(const float4*)&Bs[cb][kb*4+kl][tx*4];
                float4 b1 = *(const float4*)&Bs[cb][kb*4+kl][64 + tx*4];
                float av;
                av = a0v[kl];
                acc[0][0]+=av*b0.x; acc[0][1]+=av*b0.y; acc[0][2]+=av*b0.z; acc[0][3]+=av*b0.w;
                acc[0][4]+=av*b1.x; acc[0][5]+=av*b1.y; acc[0][6]+=av*b1.z; acc[0][7]+=av*b1.w;
                av = a1v[kl];
                acc[1][0]+=av*b0.x; acc[1][1]+=av*b0.y; acc[1][2]+=av*b0.z; acc[1][3]+=av*b0.w;
                acc[1][4]+=av*b1.x; acc[1][5]+=av*b1.y; acc[1][6]+=av*b1.z; acc[1][7]+=av*b1.w;
                av = a2v[kl];
                acc[2][0]+=av*b0.x; acc[2][1]+=av*b0.y; acc[2][2]+=av*b0.z; acc[2][3]+=av*b0.w;
                acc[2][4]+=av*b1.x; acc[2][5]+=av*b1.y; acc[2][6]+=av*b1.z; acc[2][7]+=av*b1.w;
                av = a3v[kl];
                acc[3][0]+=av*b0.x; acc[3][1]+=av*b0.y; acc[3][2]+=av*b0.z; acc[3][3]+=av*b0.w;
                acc[3][4]+=av*b1.x; acc[3][5]+=av*b1.y; acc[3][6]+=av*b1.z; acc[3][7]+=av*b1.w;
            }
        }
        __syncthreads();
    }

    // epilogue: thread covers rows m0..m0+3, cols col0+tx*4+{0..3} and +64
    int m0 = row0 + qrow*4;
    if (mode == 3) {
#pragma unroll
        for (int i = 0; i < 4; i++) {
            float* dst = &outp[(size_t)(m0 + i)*C_ + col0 + tx*4];
            *(float4*)dst      = make_float4(acc[i][0],acc[i][1],acc[i][2],acc[i][3]);
            *(float4*)(dst+64) = make_float4(acc[i][4],acc[i][5],acc[i][6],acc[i][7]);
        }
    } else {
        int b  = m0 >> 11, t0 = m0 & (T_-1);
        int d0 = tx*4;
        int h0 = col0 >> 6;       // two heads: h0 (group 0), h0+1 (group 1)
        if (mode == 2) {
#pragma unroll
            for (int i = 0; i < 4; i++) {
                float* dst0 = &g_v[((size_t)(b*H_ + h0  )*T_ + (t0+i))*HD_ + d0];
                float* dst1 = &g_v[((size_t)(b*H_ + h0+1)*T_ + (t0+i))*HD_ + d0];
                *(float4*)dst0 = make_float4(acc[i][0],acc[i][1],acc[i][2],acc[i][3]);
                *(float4*)dst1 = make_float4(acc[i][4],acc[i][5],acc[i][6],acc[i][7]);
            }
        } else {
            float* dstb = (mode == 0) ? g_q : g_k;
            size_t base0 = (size_t)(b*H_ + h0  )*HD_*T_;
            size_t base1 = (size_t)(b*H_ + h0+1)*HD_*T_;
#pragma unroll
            for (int j = 0; j < 4; j++) {
                float sc = (mode == 0) ? QSC * __ldg(&qm[d0+j]) : 1.f;
                *(float4*)&dstb[base0 + (size_t)(d0+j)*T_ + t0] =
                    make_float4(acc[0][j]*sc, acc[1][j]*sc, acc[2][j]*sc, acc[3][j]*sc);
                *(float4*)&dstb[base1 + (size_t)(d0+j)*T_ + t0] =
                    make_float4(acc[0][4+j]*sc, acc[1][4+j]*sc, acc[2][4+j]*sc, acc[3][4+j]*sc);
            }
        }
    }
}

// ---------------------------------------------------------------------------
// GEMM-tiled sparse top-4 causal attention, cp.async double-buffered K tiles.
// CTA: 64 queries x all keys (tiles of 64). 256 threads = 16 qrow x 16 kcol,
// 4q x 4k micro-tile; per-thread top-4 over its key slice; smem merge; V gather.
// ---------------------------------------------------------------------------
#define MQ 64
#define NK 64

struct AttnSmem {
    union {
        struct { float Qs[64][64]; float Ks[2][64][64]; } t;           // 48 KB
        struct { float cv[64][65]; int ci[64][65];
                 float ws[64][4];  int is[64][4]; } c;                 // 34.5 KB
    } u;
};

#define INS4(W0,W1,W2,W3,I0,I1,I2,I3,s,j)                                   \
    if ((s) > W3) { W3=(s); I3=(j);                                         \
        if (W3>W2){float tf_=W2;W2=W3;W3=tf_;int ti_=I2;I2=I3;I3=ti_;       \
            if (W2>W1){tf_=W1;W1=W2;W2=tf_;ti_=I1;I1=I2;I2=ti_;             \
                if (W1>W0){tf_=W0;W0=W1;W1=tf_;ti_=I0;I0=I1;I1=ti_;}}}}

__global__ __launch_bounds__(256)
void attn_kernel()
{
    __shared__ AttnSmem sm;
    int bh  = blockIdx.y;
    int q0  = (gridDim.x - 1 - blockIdx.x) * MQ;   // heavy CTAs first
    int tid = threadIdx.x;
    int qrow = tid >> 4;     // 0..15
    int kcol = tid & 15;     // 0..15

    const float* qb = g_q + (size_t)bh*HD_*T_;
    const float* kb = g_k + (size_t)bh*HD_*T_;
    const float* vb = g_v + (size_t)bh*T_*HD_;

    int lr = tid >> 2;            // 0..63 (= d)
    int lc = (tid & 3) * 16;      // 0,16,32,48

    // preload Q tile + K tile 0 (one cp.async group)
#pragma unroll
    for (int u = 0; u < 4; u++)
        cpa16(&sm.u.t.Qs[lr][lc + u*4], qb + (size_t)lr*T_ + q0 + lc + u*4);
#pragma unroll
    for (int u = 0; u < 4; u++)
        cpa16(&sm.u.t.Ks[0][lr][lc + u*4], kb + (size_t)lr*T_ + lc + u*4);
    cpa_commit();

    float w[4][4];
    int  id[4][4];
#pragma unroll
    for (int u = 0; u < 4; u++)
#pragma unroll
        for (int m = 0; m < 4; m++) { w[u][m] = -FLT_MAX; id[u][m] = 0; }

    const int ntiles = q0/NK + 1;
    for (int tile = 0; tile < ntiles; tile++) {
        if (tile + 1 < ntiles) {
            int nb = (tile + 1) & 1;
            const float* src = kb + (size_t)lr*T_ + (tile+1)*NK + lc;
#pragma unroll
            for (int u = 0; u < 4; u++)
                cpa16(&sm.u.t.Ks[nb][lr][lc + u*4], src + u*4);
            cpa_commit();
            cpa_wait<1>();
        } else {
            cpa_wait<0>();
        }
        __syncthreads();

        int cb = tile & 1;
        float accv[4][4];
#pragma unroll
        for (int u = 0; u < 4; u++)
#pragma unroll
            for (int v = 0; v < 4; v++) accv[u][v] = 0.f;

#pragma unroll 16
        for (int kk = 0; kk < 64; kk++) {
            float4 av = *(const float4*)&sm.u.t.Qs[kk][qrow*4];
            float4 bv = *(const float4*)&sm.u.t.Ks[cb][kk][kcol*4];
            accv[0][0] += av.x*bv.x; accv[0][1] += av.x*bv.y;
            accv[0][2] += av.x*bv.z; accv[0][3] += av.x*bv.w;
            accv[1][0] += av.y*bv.x; accv[1][1] += av.y*bv.y;
            accv[1][2] += av.y*bv.z; accv[1][3] += av.y*bv.w;
            accv[2][0] += av.z*bv.x; accv[2][1] += av.z*bv.y;
            accv[2][2] += av.z*bv.z; accv[2][3] += av.z*bv.w;
            accv[3][0] += av.w*bv.x; accv[3][1] += av.w*bv.y;
            accv[3][2] += av.w*bv.z; accv[3][3] += av.w*bv.w;
        }

        int jb = tile*NK + kcol*4;
        if (tile == ntiles-1) {
#pragma unroll
            for (int u = 0; u < 4; u++) {
                int qg = q0 + qrow*4 + u;
#pragma unroll
                for (int v = 0; v < 4; v++) {
                    float s = accv[u][v]; int j = jb + v;
                    if (j <= qg) { INS4(w[u][0],w[u][1],w[u][2],w[u][3],
                                        id[u][0],id[u][1],id[u][2],id[u][3], s, j); }
                }
            }
        } else {
#pragma unroll
            for (int u = 0; u < 4; u++) {
#pragma unroll
                for (int v = 0; v < 4; v++) {
                    float s = accv[u][v]; int j = jb + v;
                    INS4(w[u][0],w[u][1],w[u][2],w[u][3],
                         id[u][0],id[u][1],id[u][2],id[u][3], s, j);
                }
            }
        }
        __syncthreads();
    }

    // write per-thread candidates: cand[kcol*4+m][qrow*4+u]
#pragma unroll
    for (int u = 0; u < 4; u++) {
        int q = qrow*4 + u;
#pragma unroll
        for (int m = 0; m < 4; m++) {
            int c = kcol*4 + m;
            sm.u.c.cv[c][q] = w[u][m];
            sm.u.c.ci[c][q] = id[u][m];
        }
    }
    __syncthreads();

    if (tid < 64) {
        int q = tid, qi = q0 + q;
        float m0=-FLT_MAX, m1=-FLT_MAX, m2=-FLT_MAX, m3=-FLT_MAX;
        int   j0_=0, j1_=0, j2_=0, j3_=0;
        for (int c = 0; c < 64; c++) {
            float s = sm.u.c.cv[c][q];
            int   j = sm.u.c.ci[c][q];
            INS4(m0,m1,m2,m3,j0_,j1_,j2_,j3_, s, j);
        }
        // kth = 4th largest of (causal scores U (T-1-i) masked zeros)
        int z  = T_ - 1 - qi;
        int nz = z < 4 ? z : 4;
        int p  = (m0 > 0.f) + (m1 > 0.f) + (m2 > 0.f) + (m3 > 0.f);
        float kth;
        if (p >= 4)            kth = m3;
        else if (p + nz >= 4)  kth = 0.f;
        else kth = (nz == 0) ? m3 : (nz == 1 ? m2 : (nz == 2 ? m1 : m0));

        sm.u.c.ws[q][0] = (m0 >= kth) ? tanhf(m0) : 0.f;  sm.u.c.is[q][0] = j0_;
        sm.u.c.ws[q][1] = (m1 >= kth) ? tanhf(m1) : 0.f;  sm.u.c.is[q][1] = j1_;
        sm.u.c.ws[q][2] = (m2 >= kth) ? tanhf(m2) : 0.f;  sm.u.c.is[q][2] = j2_;
        sm.u.c.ws[q][3] = (m3 >= kth) ? tanhf(m3) : 0.f;  sm.u.c.is[q][3] = j3_;
    }
    __syncthreads();

    // V gather + Y write: thread = (q, 16-dim group)
    {
        int q = tid >> 2, g = tid & 3;
        float4 a0 = make_float4(0,0,0,0), a1 = a0, a2 = a0, a3 = a0;
#pragma unroll
        for (int m = 0; m < 4; m++) {
            float wt = sm.u.c.ws[q][m];
            const float4* vp = (const float4*)(vb + (size_t)sm.u.c.is[q][m]*HD_ + g*16);
            float4 v0 = vp[0], v1 = vp[1], v2 = vp[2], v3 = vp[3];
            a0.x += wt*v0.x; a0.y += wt*v0.y; a0.z += wt*v0.z; a0.w += wt*v0.w;
            a1.x += wt*v1.x; a1.y += wt*v1.y; a1.z += wt*v1.z; a1.w += wt*v1.w;
            a2.x += wt*v2.x; a2.y += wt*v2.y; a2.z += wt*v2.z; a2.w += wt*v2.w;
            a3.x += wt*v3.x; a3.y += wt*v3.y; a3.z += wt*v3.z; a3.w += wt*v3.w;
        }
        int b = bh / H_, h = bh % H_;
        float4* yp = (float4*)(g_y + ((size_t)b*T_ + q0 + q)*C_ + h*HD_ + g*16);
        yp[0] = a0; yp[1] = a1; yp[2] = a2; yp[3] = a3;
    }
}

// ---------------------------------------------------------------------------
extern "C" void kernel_launch(void* const* d_in, const int* in_sizes, int n_in,
                              void* d_out, int out_size)
{
    const float* x  = (const float*)d_in[0];
    const float* Wq = (const float*)d_in[1];
    const float* Wk = (const float*)d_in[2];
    const float* Wv = (const float*)d_in[3];
    const float* Wp = (const float*)d_in[4];
    const float* qm = (const float*)d_in[5];
    float* out = (float*)d_out;

    gemm64<<<dim3(C_/GBN, (B_*T_)/GBM, 3), 256>>>(x, Wq, Wk, Wv, qm, nullptr, 0);
    attn_kernel<<<dim3(T_/MQ, BH_), 256>>>();
    gemm64<<<dim3(C_/GBN, (B_*T_)/GBM, 1), 256>>>(nullptr, Wp, nullptr, nullptr, nullptr, out, 1);
}